// round 8
// baseline (speedup 1.0000x reference)
#include <cuda_runtime.h>
#include <math.h>

#define NTOK 2048
#define NH   8
#define NN   32
#define NJ   34

#define SCALE0  0.25f
#define SCALE1  0.14433756729740643f
#define SHAREDC 0.70710678118654752f
#define NEGV    -1e9f

// ---------------- scratch ----------------
__device__ float g_skv0[NTOK * 256];       // [0..128)=k_self, [128..256)=v_self
__device__ float g_skv1[NTOK * 768];       // (i, o, m): o<128 k, o>=128 v
__device__ float g_out0[NTOK * 128];
__device__ float g_out1[NTOK * 384];       // (i, c, m)
__device__ int   g_mask_mode;              // 0=byte, 1=int32, 2=float32

__device__ __forceinline__ float dot4(float4 a, float4 b) {
    return a.x*b.x + a.y*b.y + a.z*b.z + a.w*b.w;
}

__device__ __forceinline__ unsigned s2u(const void* p) {
    return (unsigned)__cvta_generic_to_shared(p);
}
__device__ __forceinline__ void cp_async16(unsigned dst, const void* src) {
    asm volatile("cp.async.cg.shared.global [%0], [%1], 16;" :: "r"(dst), "l"(src));
}

// ---------------- tiled SGEMM (C = A * B^T): 128 thr, BM=64 x BN=32 ----------------
#define BM 64
#define BN 32
#define BK 16

template<int K>
__device__ __forceinline__ void gemm_body(
    const float* __restrict__ A, const float* __restrict__ B, float* __restrict__ C,
    int lda, int eA, int ldc, int eC, int m0, int n0,
    float (*As)[BK][BM + 4], float (*Bs)[BK][BN + 4])
{
    const int t  = threadIdx.x;      // 0..127
    const int tx = t & 7;            // 8 * 4 = 32 (n)
    const int ty = t >> 3;           // 16 * 4 = 64 (m)
    const int aK = t & 15;
    const int aM = t >> 4;           // 0..7

    float acc[4][4] = {};
    float ra[8], rb[4];

    #pragma unroll
    for (int r = 0; r < 8; r++)
        ra[r] = A[(size_t)(m0 + aM + 8*r) * lda + (size_t)aK * eA];
    #pragma unroll
    for (int r = 0; r < 4; r++)
        rb[r] = B[(size_t)(n0 + aM + 8*r) * K + aK];

    int buf = 0;
    #pragma unroll
    for (int k0 = 0; k0 < K; k0 += BK) {
        #pragma unroll
        for (int r = 0; r < 8; r++) As[buf][aK][aM + 8*r] = ra[r];
        #pragma unroll
        for (int r = 0; r < 4; r++) Bs[buf][aK][aM + 8*r] = rb[r];
        __syncthreads();
        const int kn = k0 + BK;
        if (kn < K) {
            #pragma unroll
            for (int r = 0; r < 8; r++)
                ra[r] = A[(size_t)(m0 + aM + 8*r) * lda + (size_t)(kn + aK) * eA];
            #pragma unroll
            for (int r = 0; r < 4; r++)
                rb[r] = B[(size_t)(n0 + aM + 8*r) * K + (kn + aK)];
        }
        #pragma unroll
        for (int kk = 0; kk < BK; kk++) {
            float4 a = *(const float4*)&As[buf][kk][ty * 4];
            float4 b = *(const float4*)&Bs[buf][kk][tx * 4];
            float av[4] = {a.x, a.y, a.z, a.w};
            float bv[4] = {b.x, b.y, b.z, b.w};
            #pragma unroll
            for (int r = 0; r < 4; r++)
                #pragma unroll
                for (int s = 0; s < 4; s++)
                    acc[r][s] = fmaf(av[r], bv[s], acc[r][s]);
        }
        buf ^= 1;
        if (kn < K) __syncthreads();
    }
    #pragma unroll
    for (int r = 0; r < 4; r++)
        #pragma unroll
        for (int s = 0; s < 4; s++)
            C[(size_t)(m0 + ty*4 + r) * ldc + (size_t)(n0 + tx*4 + s) * eC] = acc[r][s];
}

// z==0: deg0 self-kv (K=128); z in 1..3: deg1 slice z-1 (K=64). Embeds mask detect.
__global__ __launch_bounds__(128, 8) void skv_fused_kernel(
    const float* __restrict__ feats0, const float* __restrict__ Wskv0,
    const float* __restrict__ feats1, const float* __restrict__ Wskv1,
    const unsigned int* __restrict__ mask)
{
    if (blockIdx.z == 0 && blockIdx.x == 0 && blockIdx.y == 0 && threadIdx.x == 0) {
        int allBin = 1, allFloat = 1;
        for (int k = 0; k < 128; k++) {
            unsigned v = mask[k];
            if (v != 0u && v != 1u) allBin = 0;
            if (v != 0u && v != 0x3F800000u) allFloat = 0;
        }
        g_mask_mode = allBin ? 1 : (allFloat ? 2 : 0);
    }
    __shared__ float As[2][BK][BM + 4];
    __shared__ float Bs[2][BK][BN + 4];
    const int m0 = blockIdx.y * BM, n0 = blockIdx.x * BN;
    if (blockIdx.z == 0) {
        gemm_body<128>(feats0, Wskv0, g_skv0, 128, 1, 256, 1, m0, n0, As, Bs);
    } else {
        int m = blockIdx.z - 1;
        gemm_body<64>(feats1 + m, Wskv1, g_skv1 + m, 192, 3, 768, 3, m0, n0, As, Bs);
    }
}

// z==0: y0 (x=0..3); z in 1..3: y1 slice (x<2)
__global__ __launch_bounds__(128, 8) void out_fused_kernel(
    const float* __restrict__ Wout0, const float* __restrict__ Wout1,
    float* __restrict__ out)
{
    if (blockIdx.z != 0 && blockIdx.x >= 2) return;
    __shared__ float As[2][BK][BM + 4];
    __shared__ float Bs[2][BK][BN + 4];
    const int m0 = blockIdx.y * BM, n0 = blockIdx.x * BN;
    if (blockIdx.z == 0) {
        gemm_body<128>(g_out0, Wout0, out, 128, 1, 128, 1, m0, n0, As, Bs);
    } else {
        int m = blockIdx.z - 1;
        gemm_body<128>(g_out1 + m, Wout1, out + (size_t)NTOK * 128 + m,
                       384, 3, 192, 3, m0, n0, As, Bs);
    }
}

// ---------------- attention core: one token per 512-thread block ----------------
// Dynamic smem: es[1024] (edges, 4KB) ++ vs1[34*384] (51KB); two cp.async groups.
#define DYN_FLOATS (1024 + NJ * 384)
#define DYN_BYTES  (DYN_FLOATS * 4)

__global__ __launch_bounds__(512, 3) void attn_kernel(
    const float* __restrict__ q0, const float* __restrict__ q1,
    const float* __restrict__ k0, const float* __restrict__ k1,
    const float* __restrict__ v0, const float* __restrict__ v1,
    const float* __restrict__ edges, const float* __restrict__ wbias,
    const float* __restrict__ self_bias, const float* __restrict__ null_bias,
    const float* __restrict__ nk0, const float* __restrict__ nv0,
    const float* __restrict__ nk1, const float* __restrict__ nv1,
    const float* __restrict__ hw1, const void* __restrict__ nbmask)
{
    const int i = blockIdx.x;
    const int t = threadIdx.x;

    extern __shared__ __align__(16) float dsm[];
    float* es  = dsm;                 // [32][32] edges
    float* vs1 = dsm + 1024;          // [NJ][384]

    __shared__ __align__(16) float q0s[128];   // pre-scaled
    __shared__ __align__(16) float q1s[384];   // pre-scaled
    __shared__ __align__(16) float wb[256];    // pre-scaled
    __shared__ float sbS[NH], nbS[NH];
    __shared__ float totS[NH * NJ];
    __shared__ float attnS[NH * NJ];
    __shared__ const float* kp0S[NJ];
    __shared__ const float* kp1S[NJ];
    __shared__ const float* vp0S[NJ];
    __shared__ int validS[NJ];
    __shared__ __align__(16) float red1[512];
    __shared__ __align__(16) float red3[512];

    // ---- group 0: edges (small, needed for logits) ----
    if (t < 256)
        cp_async16(s2u(es + t * 4), edges + (size_t)i * 1024 + t * 4);
    asm volatile("cp.async.commit_group;" ::: "memory");

    // ---- group 1: v1 rows (big, needed only after softmax) ----
    for (int c = t; c < NJ * 96; c += 512) {
        int j = c / 96, q = c - j * 96;
        const float* src;
        if (j == 0)      src = nv1 + q * 4;
        else if (j == 1) src = g_skv1 + (size_t)i * 768 + 384 + q * 4;
        else             src = v1 + ((size_t)i * NN + (j - 2)) * 384 + q * 4;
        cp_async16(s2u(vs1 + j * 384 + q * 4), src);
    }
    asm volatile("cp.async.commit_group;" ::: "memory");

    // ---- stage ----
    if (t < 128) {
        q0s[t] = q0[(size_t)i * 128 + t] * (SCALE0 * SHAREDC);
        wb[t]       = wbias[t] * SHAREDC;
        wb[t + 128] = wbias[t + 128] * SHAREDC;
    } else {
        int o = t - 128;                  // 0..383
        int h = o / 48;
        float x = hw1[h];
        float sp = (x > 20.f) ? x : log1pf(__expf(x));
        q1s[o] = q1[(size_t)i * 384 + o] * (sp * SCALE1 * SHAREDC);
    }
    if (t >= 128 && t < 128 + NJ) {
        int j = t - 128;
        if (j == 0) {
            kp0S[0] = nk0; kp1S[0] = nk1; vp0S[0] = nv0; validS[0] = 1;
        } else if (j == 1) {
            kp0S[1] = g_skv0 + (size_t)i * 256;
            vp0S[1] = g_skv0 + (size_t)i * 256 + 128;
            kp1S[1] = g_skv1 + (size_t)i * 768;
            validS[1] = 1;
        } else {
            size_t r = (size_t)i * NN + (j - 2);
            kp0S[j] = k0 + r * 128;
            kp1S[j] = k1 + r * 384;
            vp0S[j] = v0 + r * 128;
            int mm = g_mask_mode;
            int mi = i * NN + (j - 2);
            int valid;
            if (mm == 1)      valid = ((const int*)nbmask)[mi] != 0;
            else if (mm == 2) valid = ((const float*)nbmask)[mi] != 0.f;
            else              valid = ((const unsigned char*)nbmask)[mi] != 0;
            validS[j] = valid;
        }
    }
    if (t >= 168 && t < 176) {
        int h = t - 168;
        sbS[h] = self_bias[h] * SHAREDC;
        nbS[h] = null_bias[h] * SHAREDC;
    }
    // wait for edges group (v1 group may still be in flight)
    asm volatile("cp.async.wait_group 1;" ::: "memory");
    __syncthreads();

    // ---- logits: warp per j (16 warps) ----
    {
        const int w = t >> 5, lane = t & 31;
        const int h = lane >> 2, part = lane & 3;
        const float4 qa = ((const float4*)q0s)[lane];
        const float4* q1v = (const float4*)(q1s + 12 * lane);
        const float4 qb0 = q1v[0], qb1 = q1v[1], qb2 = q1v[2];

        for (int j = w; j < NJ; j += 16) {
            const float4* k0p = (const float4*)kp0S[j];
            const float4* k1p = (const float4*)(kp1S[j] + 12 * lane);
            float4 ka  = k0p[lane];
            float4 kb0 = k1p[0], kb1 = k1p[1], kb2 = k1p[2];
            float p = dot4(qa, ka) + dot4(qb0, kb0) + dot4(qb1, kb1) + dot4(qb2, kb2);
            if (j >= 2) {
                const float4* ep  = (const float4*)(es + (j - 2) * 32 + part * 8);
                const float4* wbp = (const float4*)(wb + h * 32 + part * 8);
                p += dot4(ep[0], wbp[0]) + dot4(ep[1], wbp[1]);
            }
            p += __shfl_down_sync(0xffffffffu, p, 2);
            p += __shfl_down_sync(0xffffffffu, p, 1);
            if (part == 0) {
                if (j == 1) p += sbS[h];
                if (j == 0) p += nbS[h];
                totS[h * NJ + j] = validS[j] ? p : NEGV;
            }
        }
    }
    __syncthreads();

    // ---- softmax: warps 0..7, warp w = head w over 34 logits ----
    if (t < 256) {
        const int w = t >> 5, lane = t & 31;
        float x1 = totS[w * NJ + lane];
        float x2 = (lane < 2) ? totS[w * NJ + 32 + lane] : -2e9f;
        float mx = fmaxf(x1, x2);
        #pragma unroll
        for (int o = 16; o > 0; o >>= 1) mx = fmaxf(mx, __shfl_xor_sync(0xffffffffu, mx, o));
        float e1 = __expf(x1 - mx);
        float e2 = (lane < 2) ? __expf(x2 - mx) : 0.f;
        float s = e1 + e2;
        #pragma unroll
        for (int o = 16; o > 0; o >>= 1) s += __shfl_xor_sync(0xffffffffu, s, o);
        float inv = 1.f / s;
        attnS[w * NJ + lane] = e1 * inv;
        if (lane < 2) attnS[w * NJ + 32 + lane] = e2 * inv;
    }
    asm volatile("cp.async.wait_group 0;" ::: "memory");
    __syncthreads();

    // ---- V accumulation: v1 from smem, v0 from global (prefetched) ----
    {
        const int g  = t >> 7;        // 0..3: handles j == g (mod 4)
        const int tl = t & 127;
        const bool isV1 = (tl < 96);  // warps 0-2 of the group: v1; warp 3: v0

        float4 acc = make_float4(0.f, 0.f, 0.f, 0.f);
        if (isV1) {
            const int off = 4 * tl;
            const int hv  = tl / 12;
            const float* vbase = vs1 + off;
            #pragma unroll
            for (int j = g; j < NJ; j += 4) {
                float wgt = attnS[hv * NJ + j];
                float4 v = *(const float4*)(vbase + j * 384);
                acc.x = fmaf(wgt, v.x, acc.x);
                acc.y = fmaf(wgt, v.y, acc.y);
                acc.z = fmaf(wgt, v.z, acc.z);
                acc.w = fmaf(wgt, v.w, acc.w);
            }
        } else {
            const int off = 4 * (tl - 96);
            const int hv  = (tl - 96) / 4;
            float4 cur = *(const float4*)(vp0S[g] + off);
            float4 nx1 = make_float4(0.f, 0.f, 0.f, 0.f);
            if (g + 4 < NJ) nx1 = *(const float4*)(vp0S[g + 4] + off);
            #pragma unroll 1
            for (int j = g; j < NJ; j += 4) {
                float4 nx2 = make_float4(0.f, 0.f, 0.f, 0.f);
                int jn = j + 8;
                if (jn < NJ) nx2 = *(const float4*)(vp0S[jn] + off);
                float wgt = attnS[hv * NJ + j];
                acc.x = fmaf(wgt, cur.x, acc.x);
                acc.y = fmaf(wgt, cur.y, acc.y);
                acc.z = fmaf(wgt, cur.z, acc.z);
                acc.w = fmaf(wgt, cur.w, acc.w);
                cur = nx1; nx1 = nx2;
            }
        }
        const int off = isV1 ? 4 * tl : 4 * (tl - 96);
        if (g == 1) ((float4*)red1)[tl] = acc;
        if (g == 3) ((float4*)red3)[tl] = acc;
        __syncthreads();
        if (g == 0) {
            float4 o = ((const float4*)red1)[tl];
            acc.x += o.x; acc.y += o.y; acc.z += o.z; acc.w += o.w;
            ((float4*)red1)[tl] = acc;
        }
        if (g == 2) {
            float4 o = ((const float4*)red3)[tl];
            acc.x += o.x; acc.y += o.y; acc.z += o.z; acc.w += o.w;
        }
        __syncthreads();
        if (g == 2) {
            float4 o = ((const float4*)red1)[tl];
            acc.x += o.x; acc.y += o.y; acc.z += o.z; acc.w += o.w;
            if (isV1) *(float4*)(g_out1 + (size_t)i * 384 + off) = acc;
            else      *(float4*)(g_out0 + (size_t)i * 128 + off) = acc;
        }
    }
}

// ---------------- launch ----------------
extern "C" void kernel_launch(void* const* d_in, const int* in_sizes, int n_in,
                              void* d_out, int out_size)
{
    const float* q0     = (const float*)d_in[0];
    const float* k0     = (const float*)d_in[1];
    const float* v0     = (const float*)d_in[2];
    const float* q1     = (const float*)d_in[3];
    const float* k1     = (const float*)d_in[4];
    const float* v1     = (const float*)d_in[5];
    const float* feats0 = (const float*)d_in[6];
    const float* feats1 = (const float*)d_in[7];
    const float* edges  = (const float*)d_in[8];
    const float* Wskv0  = (const float*)d_in[9];
    const float* Wskv1  = (const float*)d_in[10];
    const float* Wbias  = (const float*)d_in[11];
    const float* sbias  = (const float*)d_in[12];
    const float* nbias  = (const float*)d_in[13];
    const float* nk0    = (const float*)d_in[14];
    const float* nv0    = (const float*)d_in[15];
    const float* nk1    = (const float*)d_in[16];
    const float* nv1    = (const float*)d_in[17];
    const float* hw1    = (const float*)d_in[18];
    const float* Wout0  = (const float*)d_in[19];
    const float* Wout1  = (const float*)d_in[20];
    const void*  nbm    = d_in[21];
    float* out = (float*)d_out;

    static int smem_set = 0;
    if (!smem_set) {
        cudaFuncSetAttribute(attn_kernel,
                             cudaFuncAttributeMaxDynamicSharedMemorySize, DYN_BYTES);
        smem_set = 1;
    }

    skv_fused_kernel<<<dim3(256 / BN, NTOK / BM, 4), 128>>>(
        feats0, Wskv0, feats1, Wskv1, (const unsigned int*)nbm);

    attn_kernel<<<NTOK, 512, DYN_BYTES>>>(q0, q1, k0, k1, v0, v1, edges, Wbias,
                                          sbias, nbias, nk0, nv0, nk1, nv1, hw1, nbm);

    out_fused_kernel<<<dim3(128 / BN, NTOK / BM, 4), 128>>>(Wout0, Wout1, out);
}

// round 9
// speedup vs baseline: 1.0196x; 1.0196x over previous
#include <cuda_runtime.h>
#include <math.h>
#include <mma.h>

using namespace nvcuda;

#define NTOK 2048
#define NH   8
#define NN   32
#define NJ   34

#define SCALE0  0.25f
#define SCALE1  0.14433756729740643f
#define SHAREDC 0.70710678118654752f
#define NEGV    -1e9f

// ---------------- scratch ----------------
__device__ float g_skv0[NTOK * 256];       // [0..128)=k_self, [128..256)=v_self
__device__ float g_skv1[NTOK * 768];       // (i, o, m): o<128 k, o>=128 v
__device__ float g_out0[NTOK * 128];
__device__ float g_out1[NTOK * 384];       // (i, c, m)
__device__ int   g_mask_mode;              // 0=byte, 1=int32, 2=float32

__device__ __forceinline__ float dot4(float4 a, float4 b) {
    return a.x*b.x + a.y*b.y + a.z*b.z + a.w*b.w;
}
__device__ __forceinline__ unsigned s2u(const void* p) {
    return (unsigned)__cvta_generic_to_shared(p);
}
__device__ __forceinline__ void cp_async16(unsigned dst, const void* src) {
    asm volatile("cp.async.cg.shared.global [%0], [%1], 16;" :: "r"(dst), "l"(src));
}

// ---------------- tf32 wmma GEMM (C = A * B^T): 128 thr, 64x64 tile, BK=32 ----------
#define GBM 64
#define GBN 64
#define GBK 32
#define ALD 40   // GBK + 8
#define CLD 72
#define SMEM_FLOATS (GBM * ALD + GBN * ALD)   // 5120 (Cs[64*72]=4608 reuses this)

template<int K>
__device__ __forceinline__ void wmma_gemm_body(
    const float* __restrict__ A, const float* __restrict__ B, float* __restrict__ C,
    int lda, int eA, int ldc, int eC, int m0, int n0, float* sm)
{
    float* As = sm;                // [GBM][ALD]
    float* Bs = sm + GBM * ALD;    // [GBN][ALD]
    float* Cs = sm;                // reuse: [GBM][CLD]

    const int t = threadIdx.x;     // 0..127
    const int warp = t >> 5;
    const int wm = warp >> 1;      // 0..1 -> m offset 32*wm
    const int wn = warp & 1;       // 0..1 -> n offset 32*wn

    wmma::fragment<wmma::accumulator, 16, 16, 8, float> acc[2][2];
    #pragma unroll
    for (int r = 0; r < 2; r++)
        #pragma unroll
        for (int s = 0; s < 2; s++)
            wmma::fill_fragment(acc[r][s], 0.0f);

    const int srow = t >> 1;            // 0..63
    const int skb  = (t & 1) * 16;      // 0 or 16

    #pragma unroll
    for (int k0 = 0; k0 < K; k0 += GBK) {
        if (k0 > 0) __syncthreads();
        // stage A tile (convert to tf32)
        {
            const float* ap = A + (size_t)(m0 + srow) * lda + (size_t)(k0 + skb) * eA;
            float* dst = As + srow * ALD + skb;
            #pragma unroll
            for (int u = 0; u < 16; u++)
                dst[u] = wmma::__float_to_tf32(ap[(size_t)u * eA]);
        }
        // stage B tile (row-major [N,K], contiguous)
        {
            const float* bp = B + (size_t)(n0 + srow) * K + (k0 + skb);
            float* dst = Bs + srow * ALD + skb;
            #pragma unroll
            for (int u = 0; u < 16; u++)
                dst[u] = wmma::__float_to_tf32(bp[u]);
        }
        __syncthreads();
        #pragma unroll
        for (int ks = 0; ks < GBK / 8; ks++) {
            wmma::fragment<wmma::matrix_a, 16, 16, 8, wmma::precision::tf32, wmma::row_major> af[2];
            wmma::fragment<wmma::matrix_b, 16, 16, 8, wmma::precision::tf32, wmma::col_major> bf[2];
            wmma::load_matrix_sync(af[0], As + (wm * 32)      * ALD + ks * 8, ALD);
            wmma::load_matrix_sync(af[1], As + (wm * 32 + 16) * ALD + ks * 8, ALD);
            wmma::load_matrix_sync(bf[0], Bs + (wn * 32)      * ALD + ks * 8, ALD);
            wmma::load_matrix_sync(bf[1], Bs + (wn * 32 + 16) * ALD + ks * 8, ALD);
            #pragma unroll
            for (int r = 0; r < 2; r++)
                #pragma unroll
                for (int s = 0; s < 2; s++)
                    wmma::mma_sync(acc[r][s], af[r], bf[s], acc[r][s]);
        }
    }
    __syncthreads();
    #pragma unroll
    for (int r = 0; r < 2; r++)
        #pragma unroll
        for (int s = 0; s < 2; s++)
            wmma::store_matrix_sync(Cs + (wm * 32 + 16 * r) * CLD + wn * 32 + 16 * s,
                                    acc[r][s], CLD, wmma::mem_row_major);
    __syncthreads();
    for (int idx = t; idx < GBM * GBN; idx += 128) {
        int r = idx >> 6, c = idx & 63;
        C[(size_t)(m0 + r) * ldc + (size_t)(n0 + c) * eC] = Cs[r * CLD + c];
    }
}

// z==0: deg0 self-kv (K=128); z in 1..3: deg1 slice z-1 (K=64). Embeds mask detect.
__global__ __launch_bounds__(128) void skv_fused_kernel(
    const float* __restrict__ feats0, const float* __restrict__ Wskv0,
    const float* __restrict__ feats1, const float* __restrict__ Wskv1,
    const unsigned int* __restrict__ mask)
{
    if (blockIdx.z == 0 && blockIdx.x == 0 && blockIdx.y == 0 && threadIdx.x == 0) {
        int allBin = 1, allFloat = 1;
        for (int k = 0; k < 128; k++) {
            unsigned v = mask[k];
            if (v != 0u && v != 1u) allBin = 0;
            if (v != 0u && v != 0x3F800000u) allFloat = 0;
        }
        g_mask_mode = allBin ? 1 : (allFloat ? 2 : 0);
    }
    __shared__ __align__(16) float sm[SMEM_FLOATS];
    const int m0 = blockIdx.y * GBM, n0 = blockIdx.x * GBN;
    if (blockIdx.z == 0) {
        wmma_gemm_body<128>(feats0, Wskv0, g_skv0, 128, 1, 256, 1, m0, n0, sm);
    } else {
        int m = blockIdx.z - 1;
        wmma_gemm_body<64>(feats1 + m, Wskv1, g_skv1 + m, 192, 3, 768, 3, m0, n0, sm);
    }
}

// z==0: y0 (x=0..1); z in 1..3: y1 slice (x==0 only)
__global__ __launch_bounds__(128) void out_fused_kernel(
    const float* __restrict__ Wout0, const float* __restrict__ Wout1,
    float* __restrict__ out)
{
    if (blockIdx.z != 0 && blockIdx.x != 0) return;
    __shared__ __align__(16) float sm[SMEM_FLOATS];
    const int m0 = blockIdx.y * GBM, n0 = blockIdx.x * GBN;
    if (blockIdx.z == 0) {
        wmma_gemm_body<128>(g_out0, Wout0, out, 128, 1, 128, 1, m0, n0, sm);
    } else {
        int m = blockIdx.z - 1;
        wmma_gemm_body<128>(g_out1 + m, Wout1, out + (size_t)NTOK * 128 + m,
                            384, 3, 192, 3, m0, n0, sm);
    }
}

// ---------------- attention core (R7 config): one token per 512-thread block ----
// Dynamic smem: vs0[34*128] ++ vs1[34*384]  (69,632 bytes), filled by cp.async
#define VS_BYTES ((NJ * 128 + NJ * 384) * 4)

__global__ __launch_bounds__(512, 2) void attn_kernel(
    const float* __restrict__ q0, const float* __restrict__ q1,
    const float* __restrict__ k0, const float* __restrict__ k1,
    const float* __restrict__ v0, const float* __restrict__ v1,
    const float* __restrict__ edges, const float* __restrict__ wbias,
    const float* __restrict__ self_bias, const float* __restrict__ null_bias,
    const float* __restrict__ nk0, const float* __restrict__ nv0,
    const float* __restrict__ nk1, const float* __restrict__ nv1,
    const float* __restrict__ hw1, const void* __restrict__ nbmask)
{
    const int i = blockIdx.x;
    const int t = threadIdx.x;

    extern __shared__ __align__(16) float vsmem[];
    float* vs0 = vsmem;                 // [NJ][128]
    float* vs1 = vsmem + NJ * 128;      // [NJ][384]

    __shared__ __align__(16) float q0s[128];
    __shared__ __align__(16) float q1s[384];
    __shared__ __align__(16) float wb[256];
    __shared__ float sbS[NH], nbS[NH];
    __shared__ float totS[NH * NJ];
    __shared__ float attnS[NH * NJ];
    __shared__ const float* kp0S[NJ];
    __shared__ const float* kp1S[NJ];
    __shared__ int validS[NJ];
    __shared__ __align__(16) float red1[512];
    __shared__ __align__(16) float red3[512];

    // ---- issue async V copies first ----
    {
        for (int c = t; c < NJ * 32; c += 512) {
            int j = c >> 5, q = c & 31;
            const float* src;
            if (j == 0)      src = nv0 + q * 4;
            else if (j == 1) src = g_skv0 + (size_t)i * 256 + 128 + q * 4;
            else             src = v0 + ((size_t)i * NN + (j - 2)) * 128 + q * 4;
            cp_async16(s2u(vs0 + j * 128 + q * 4), src);
        }
        for (int c = t; c < NJ * 96; c += 512) {
            int j = c / 96, q = c - j * 96;
            const float* src;
            if (j == 0)      src = nv1 + q * 4;
            else if (j == 1) src = g_skv1 + (size_t)i * 768 + 384 + q * 4;
            else             src = v1 + ((size_t)i * NN + (j - 2)) * 384 + q * 4;
            cp_async16(s2u(vs1 + j * 384 + q * 4), src);
        }
        asm volatile("cp.async.commit_group;" ::: "memory");
    }

    // ---- stage ----
    if (t < 128) {
        q0s[t] = q0[(size_t)i * 128 + t] * (SCALE0 * SHAREDC);
        wb[t]       = wbias[t] * SHAREDC;
        wb[t + 128] = wbias[t + 128] * SHAREDC;
    } else {
        int o = t - 128;
        int h = o / 48;
        float x = hw1[h];
        float sp = (x > 20.f) ? x : log1pf(__expf(x));
        q1s[o] = q1[(size_t)i * 384 + o] * (sp * SCALE1 * SHAREDC);
    }
    if (t >= 128 && t < 128 + NJ) {
        int j = t - 128;
        if (j == 0) {
            kp0S[0] = nk0; kp1S[0] = nk1; validS[0] = 1;
        } else if (j == 1) {
            kp0S[1] = g_skv0 + (size_t)i * 256;
            kp1S[1] = g_skv1 + (size_t)i * 768;
            validS[1] = 1;
        } else {
            size_t r = (size_t)i * NN + (j - 2);
            kp0S[j] = k0 + r * 128;
            kp1S[j] = k1 + r * 384;
            int mm = g_mask_mode;
            int mi = i * NN + (j - 2);
            int valid;
            if (mm == 1)      valid = ((const int*)nbmask)[mi] != 0;
            else if (mm == 2) valid = ((const float*)nbmask)[mi] != 0.f;
            else              valid = ((const unsigned char*)nbmask)[mi] != 0;
            validS[j] = valid;
        }
    }
    if (t >= 168 && t < 176) {
        int h = t - 168;
        sbS[h] = self_bias[h] * SHAREDC;
        nbS[h] = null_bias[h] * SHAREDC;
    }
    __syncthreads();

    // ---- logits: warp per j (16 warps) ----
    {
        const int w = t >> 5, lane = t & 31;
        const int h = lane >> 2, part = lane & 3;
        const float4 qa = ((const float4*)q0s)[lane];
        const float4* q1v = (const float4*)(q1s + 12 * lane);
        const float4 qb0 = q1v[0], qb1 = q1v[1], qb2 = q1v[2];

        for (int j = w; j < NJ; j += 16) {
            const float4* k0p = (const float4*)kp0S[j];
            const float4* k1p = (const float4*)(kp1S[j] + 12 * lane);
            float4 ka  = k0p[lane];
            float4 kb0 = k1p[0], kb1 = k1p[1], kb2 = k1p[2];
            float p = dot4(qa, ka) + dot4(qb0, kb0) + dot4(qb1, kb1) + dot4(qb2, kb2);
            if (j >= 2) {
                const float4* ep  = (const float4*)(edges + (size_t)i * 1024 + (j - 2) * 32 + part * 8);
                const float4* wbp = (const float4*)(wb + h * 32 + part * 8);
                p += dot4(ep[0], wbp[0]) + dot4(ep[1], wbp[1]);
            }
            p += __shfl_down_sync(0xffffffffu, p, 2);
            p += __shfl_down_sync(0xffffffffu, p, 1);
            if (part == 0) {
                if (j == 1) p += sbS[h];
                if (j == 0) p += nbS[h];
                totS[h * NJ + j] = validS[j] ? p : NEGV;
            }
        }
    }
    __syncthreads();

    // ---- softmax: warps 0..7, warp w = head w over 34 logits ----
    if (t < 256) {
        const int w = t >> 5, lane = t & 31;
        float x1 = totS[w * NJ + lane];
        float x2 = (lane < 2) ? totS[w * NJ + 32 + lane] : -2e9f;
        float mx = fmaxf(x1, x2);
        #pragma unroll
        for (int o = 16; o > 0; o >>= 1) mx = fmaxf(mx, __shfl_xor_sync(0xffffffffu, mx, o));
        float e1 = __expf(x1 - mx);
        float e2 = (lane < 2) ? __expf(x2 - mx) : 0.f;
        float s = e1 + e2;
        #pragma unroll
        for (int o = 16; o > 0; o >>= 1) s += __shfl_xor_sync(0xffffffffu, s, o);
        float inv = 1.f / s;
        attnS[w * NJ + lane] = e1 * inv;
        if (lane < 2) attnS[w * NJ + 32 + lane] = e2 * inv;
    }
    asm volatile("cp.async.wait_group 0;" ::: "memory");
    __syncthreads();

    // ---- V accumulation from smem: 4 j-parity groups x 128 float4 slots ----
    {
        const int g  = t >> 7;
        const int tl = t & 127;
        const bool isV1 = (tl < 96);
        const int off = isV1 ? 4 * tl : 4 * (tl - 96);
        const int hv  = isV1 ? (tl / 12) : ((tl - 96) / 4);
        const float* vbase = isV1 ? (vs1 + off) : (vs0 + off);
        const int vstride = isV1 ? 384 : 128;

        float4 acc = make_float4(0.f, 0.f, 0.f, 0.f);
        #pragma unroll
        for (int j = g; j < NJ; j += 4) {
            float wgt = attnS[hv * NJ + j];
            float4 v = *(const float4*)(vbase + j * vstride);
            acc.x = fmaf(wgt, v.x, acc.x);
            acc.y = fmaf(wgt, v.y, acc.y);
            acc.z = fmaf(wgt, v.z, acc.z);
            acc.w = fmaf(wgt, v.w, acc.w);
        }
        if (g == 1) ((float4*)red1)[tl] = acc;
        if (g == 3) ((float4*)red3)[tl] = acc;
        __syncthreads();
        if (g == 0) {
            float4 o = ((const float4*)red1)[tl];
            acc.x += o.x; acc.y += o.y; acc.z += o.z; acc.w += o.w;
            ((float4*)red1)[tl] = acc;
        }
        if (g == 2) {
            float4 o = ((const float4*)red3)[tl];
            acc.x += o.x; acc.y += o.y; acc.z += o.z; acc.w += o.w;
        }
        __syncthreads();
        if (g == 2) {
            float4 o = ((const float4*)red1)[tl];
            acc.x += o.x; acc.y += o.y; acc.z += o.z; acc.w += o.w;
            if (isV1) *(float4*)(g_out1 + (size_t)i * 384 + off) = acc;
            else      *(float4*)(g_out0 + (size_t)i * 128 + off) = acc;
        }
    }
}

// ---------------- launch ----------------
extern "C" void kernel_launch(void* const* d_in, const int* in_sizes, int n_in,
                              void* d_out, int out_size)
{
    const float* q0     = (const float*)d_in[0];
    const float* k0     = (const float*)d_in[1];
    const float* v0     = (const float*)d_in[2];
    const float* q1     = (const float*)d_in[3];
    const float* k1     = (const float*)d_in[4];
    const float* v1     = (const float*)d_in[5];
    const float* feats0 = (const float*)d_in[6];
    const float* feats1 = (const float*)d_in[7];
    const float* edges  = (const float*)d_in[8];
    const float* Wskv0  = (const float*)d_in[9];
    const float* Wskv1  = (const float*)d_in[10];
    const float* Wbias  = (const float*)d_in[11];
    const float* sbias  = (const float*)d_in[12];
    const float* nbias  = (const float*)d_in[13];
    const float* nk0    = (const float*)d_in[14];
    const float* nv0    = (const float*)d_in[15];
    const float* nk1    = (const float*)d_in[16];
    const float* nv1    = (const float*)d_in[17];
    const float* hw1    = (const float*)d_in[18];
    const float* Wout0  = (const float*)d_in[19];
    const float* Wout1  = (const float*)d_in[20];
    const void*  nbm    = d_in[21];
    float* out = (float*)d_out;

    static int smem_set = 0;
    if (!smem_set) {
        cudaFuncSetAttribute(attn_kernel,
                             cudaFuncAttributeMaxDynamicSharedMemorySize, VS_BYTES);
        smem_set = 1;
    }

    skv_fused_kernel<<<dim3(256 / GBN, NTOK / GBM, 4), 128>>>(
        feats0, Wskv0, feats1, Wskv1, (const unsigned int*)nbm);

    attn_kernel<<<NTOK, 512, VS_BYTES>>>(q0, q1, k0, k1, v0, v1, edges, Wbias,
                                         sbias, nbias, nk0, nv0, nk1, nv1, hw1, nbm);

    out_fused_kernel<<<dim3(128 / GBN, NTOK / GBM, 4), 128>>>(Wout0, Wout1, out);
}

// round 11
// speedup vs baseline: 1.0827x; 1.0618x over previous
#include <cuda_runtime.h>
#include <math.h>

#define NTOK 2048
#define NH   8
#define NN   32
#define NJ   34

#define SCALE0  0.25f
#define SCALE1  0.14433756729740643f
#define SHAREDC 0.70710678118654752f
#define NEGV    -1e9f

// ---------------- scratch ----------------
__device__ float g_skv0[NTOK * 256];       // [0..128)=k_self, [128..256)=v_self
__device__ float g_skv1[NTOK * 768];       // (i, o, m): o<128 k, o>=128 v
__device__ float g_out0[NTOK * 128];
__device__ float g_out1[NTOK * 384];       // (i, c, m)
__device__ float g_attn[NTOK * 288];       // per token: [NH][NJ] weights (272 used)
__device__ int   g_mask_mode;              // 0=byte, 1=int32, 2=float32

__device__ __forceinline__ float dot4(float4 a, float4 b) {
    return a.x*b.x + a.y*b.y + a.z*b.z + a.w*b.w;
}

// ---------------- tiled SGEMM (C = A * B^T): 128 thr, BM=64 x BN=32 (R4) ----------------
#define BM 64
#define BN 32
#define BK 16

template<int K>
__device__ __forceinline__ void gemm_body(
    const float* __restrict__ A, const float* __restrict__ B, float* __restrict__ C,
    int lda, int eA, int ldc, int eC, int m0, int n0,
    float (*As)[BK][BM + 4], float (*Bs)[BK][BN + 4])
{
    const int t  = threadIdx.x;      // 0..127
    const int tx = t & 7;            // 8 * 4 = 32 (n)
    const int ty = t >> 3;           // 16 * 4 = 64 (m)
    const int aK = t & 15;
    const int aM = t >> 4;           // 0..7

    float acc[4][4] = {};
    float ra[8], rb[4];

    #pragma unroll
    for (int r = 0; r < 8; r++)
        ra[r] = A[(size_t)(m0 + aM + 8*r) * lda + (size_t)aK * eA];
    #pragma unroll
    for (int r = 0; r < 4; r++)
        rb[r] = B[(size_t)(n0 + aM + 8*r) * K + aK];

    int buf = 0;
    #pragma unroll
    for (int k0 = 0; k0 < K; k0 += BK) {
        #pragma unroll
        for (int r = 0; r < 8; r++) As[buf][aK][aM + 8*r] = ra[r];
        #pragma unroll
        for (int r = 0; r < 4; r++) Bs[buf][aK][aM + 8*r] = rb[r];
        __syncthreads();
        const int kn = k0 + BK;
        if (kn < K) {
            #pragma unroll
            for (int r = 0; r < 8; r++)
                ra[r] = A[(size_t)(m0 + aM + 8*r) * lda + (size_t)(kn + aK) * eA];
            #pragma unroll
            for (int r = 0; r < 4; r++)
                rb[r] = B[(size_t)(n0 + aM + 8*r) * K + (kn + aK)];
        }
        #pragma unroll
        for (int kk = 0; kk < BK; kk++) {
            float4 a = *(const float4*)&As[buf][kk][ty * 4];
            float4 b = *(const float4*)&Bs[buf][kk][tx * 4];
            float av[4] = {a.x, a.y, a.z, a.w};
            float bv[4] = {b.x, b.y, b.z, b.w};
            #pragma unroll
            for (int r = 0; r < 4; r++)
                #pragma unroll
                for (int s = 0; s < 4; s++)
                    acc[r][s] = fmaf(av[r], bv[s], acc[r][s]);
        }
        buf ^= 1;
        if (kn < K) __syncthreads();
    }
    #pragma unroll
    for (int r = 0; r < 4; r++)
        #pragma unroll
        for (int s = 0; s < 4; s++)
            C[(size_t)(m0 + ty*4 + r) * ldc + (size_t)(n0 + tx*4 + s) * eC] = acc[r][s];
}

// z==0: deg0 self-kv (K=128); z in 1..3: deg1 slice z-1 (K=64). Embeds mask detect.
__global__ __launch_bounds__(128, 8) void skv_fused_kernel(
    const float* __restrict__ feats0, const float* __restrict__ Wskv0,
    const float* __restrict__ feats1, const float* __restrict__ Wskv1,
    const unsigned int* __restrict__ mask)
{
    if (blockIdx.z == 0 && blockIdx.x == 0 && blockIdx.y == 0 && threadIdx.x == 0) {
        int allBin = 1, allFloat = 1;
        for (int k = 0; k < 128; k++) {
            unsigned v = mask[k];
            if (v != 0u && v != 1u) allBin = 0;
            if (v != 0u && v != 0x3F800000u) allFloat = 0;
        }
        g_mask_mode = allBin ? 1 : (allFloat ? 2 : 0);
    }
    __shared__ float As[2][BK][BM + 4];
    __shared__ float Bs[2][BK][BN + 4];
    const int m0 = blockIdx.y * BM, n0 = blockIdx.x * BN;
    if (blockIdx.z == 0) {
        gemm_body<128>(feats0, Wskv0, g_skv0, 128, 1, 256, 1, m0, n0, As, Bs);
    } else {
        int m = blockIdx.z - 1;
        gemm_body<64>(feats1 + m, Wskv1, g_skv1 + m, 192, 3, 768, 3, m0, n0, As, Bs);
    }
}

// z==0: y0 (x=0..3); z in 1..3: y1 slice (x<2)
__global__ __launch_bounds__(128, 8) void out_fused_kernel(
    const float* __restrict__ Wout0, const float* __restrict__ Wout1,
    float* __restrict__ out)
{
    if (blockIdx.z != 0 && blockIdx.x >= 2) return;
    __shared__ float As[2][BK][BM + 4];
    __shared__ float Bs[2][BK][BN + 4];
    const int m0 = blockIdx.y * BM, n0 = blockIdx.x * BN;
    if (blockIdx.z == 0) {
        gemm_body<128>(g_out0, Wout0, out, 128, 1, 128, 1, m0, n0, As, Bs);
    } else {
        int m = blockIdx.z - 1;
        gemm_body<128>(g_out1 + m, Wout1, out + (size_t)NTOK * 128 + m,
                       384, 3, 192, 3, m0, n0, As, Bs);
    }
}

// ---------------- logits + softmax: one token per 256-thread block ----------------
__global__ __launch_bounds__(256) void logits_kernel(
    const float* __restrict__ q0, const float* __restrict__ q1,
    const float* __restrict__ k0, const float* __restrict__ k1,
    const float* __restrict__ edges, const float* __restrict__ wbias,
    const float* __restrict__ self_bias, const float* __restrict__ null_bias,
    const float* __restrict__ nk0, const float* __restrict__ nk1,
    const float* __restrict__ hw1, const void* __restrict__ nbmask)
{
    const int i = blockIdx.x;
    const int t = threadIdx.x;

    __shared__ __align__(16) float q0s[128];   // pre-scaled
    __shared__ __align__(16) float q1s[384];   // pre-scaled
    __shared__ __align__(16) float wb[256];    // pre-scaled
    __shared__ float sbS[NH], nbS[NH];
    __shared__ float totS[NH * NJ];
    __shared__ float attnS[NH * NJ];
    __shared__ const float* kp0S[NJ];
    __shared__ const float* kp1S[NJ];
    __shared__ int validS[NJ];

    // ---- stage ----
    if (t < 128) {
        q0s[t] = q0[(size_t)i * 128 + t] * (SCALE0 * SHAREDC);
        wb[t]       = wbias[t] * SHAREDC;
        wb[t + 128] = wbias[t + 128] * SHAREDC;
    } else {
        int o = t - 128;                 // 0..127
        int h = o / 48;
        float x = hw1[h];
        float sp = (x > 20.f) ? x : log1pf(__expf(x));
        q1s[o] = q1[(size_t)i * 384 + o] * (sp * SCALE1 * SHAREDC);
        int o2 = o + 128;
        int h2 = o2 / 48;
        float x2 = hw1[h2];
        float sp2 = (x2 > 20.f) ? x2 : log1pf(__expf(x2));
        q1s[o2] = q1[(size_t)i * 384 + o2] * (sp2 * SCALE1 * SHAREDC);
        int o3 = o + 256;
        int h3 = o3 / 48;
        float x3 = hw1[h3];
        float sp3 = (x3 > 20.f) ? x3 : log1pf(__expf(x3));
        q1s[o3] = q1[(size_t)i * 384 + o3] * (sp3 * SCALE1 * SHAREDC);
    }
    if (t >= 128 && t < 128 + NJ) {
        int j = t - 128;
        if (j == 0) {
            kp0S[0] = nk0; kp1S[0] = nk1; validS[0] = 1;
        } else if (j == 1) {
            kp0S[1] = g_skv0 + (size_t)i * 256;
            kp1S[1] = g_skv1 + (size_t)i * 768;
            validS[1] = 1;
        } else {
            size_t r = (size_t)i * NN + (j - 2);
            kp0S[j] = k0 + r * 128;
            kp1S[j] = k1 + r * 384;
            int mm = g_mask_mode;
            int mi = i * NN + (j - 2);
            int valid;
            if (mm == 1)      valid = ((const int*)nbmask)[mi] != 0;
            else if (mm == 2) valid = ((const float*)nbmask)[mi] != 0.f;
            else              valid = ((const unsigned char*)nbmask)[mi] != 0;
            validS[j] = valid;
        }
    }
    if (t >= 168 && t < 176) {
        int h = t - 168;
        sbS[h] = self_bias[h] * SHAREDC;
        nbS[h] = null_bias[h] * SHAREDC;
    }
    __syncthreads();

    // ---- logits: warp per j (8 warps, ~4.25 rounds), lane = (h, part) ----
    {
        const int w = t >> 5, lane = t & 31;
        const int h = lane >> 2, part = lane & 3;
        const float4 qa = ((const float4*)q0s)[lane];
        const float4* q1v = (const float4*)(q1s + 12 * lane);
        const float4 qb0 = q1v[0], qb1 = q1v[1], qb2 = q1v[2];

        for (int j = w; j < NJ; j += 8) {
            const float4* k0p = (const float4*)kp0S[j];
            const float4* k1p = (const float4*)(kp1S[j] + 12 * lane);
            float4 ka  = k0p[lane];
            float4 kb0 = k1p[0], kb1 = k1p[1], kb2 = k1p[2];
            float p = dot4(qa, ka) + dot4(qb0, kb0) + dot4(qb1, kb1) + dot4(qb2, kb2);
            if (j >= 2) {
                const float4* ep  = (const float4*)(edges + (size_t)i * 1024 + (j - 2) * 32 + part * 8);
                const float4* wbp = (const float4*)(wb + h * 32 + part * 8);
                p += dot4(ep[0], wbp[0]) + dot4(ep[1], wbp[1]);
            }
            p += __shfl_down_sync(0xffffffffu, p, 2);
            p += __shfl_down_sync(0xffffffffu, p, 1);
            if (part == 0) {
                if (j == 1) p += sbS[h];
                if (j == 0) p += nbS[h];
                totS[h * NJ + j] = validS[j] ? p : NEGV;
            }
        }
    }
    __syncthreads();

    // ---- softmax: warp w = head w ----
    {
        const int w = t >> 5, lane = t & 31;
        float x1 = totS[w * NJ + lane];
        float x2 = (lane < 2) ? totS[w * NJ + 32 + lane] : -2e9f;
        float mx = fmaxf(x1, x2);
        #pragma unroll
        for (int o = 16; o > 0; o >>= 1) mx = fmaxf(mx, __shfl_xor_sync(0xffffffffu, mx, o));
        float e1 = __expf(x1 - mx);
        float e2 = (lane < 2) ? __expf(x2 - mx) : 0.f;
        float s = e1 + e2;
        #pragma unroll
        for (int o = 16; o > 0; o >>= 1) s += __shfl_xor_sync(0xffffffffu, s, o);
        float inv = 1.f / s;
        attnS[w * NJ + lane] = e1 * inv;
        if (lane < 2) attnS[w * NJ + 32 + lane] = e2 * inv;
    }
    __syncthreads();
    // FIX: NH*NJ = 272 > 256 threads -> strided store
    for (int l = t; l < NH * NJ; l += 256)
        g_attn[(size_t)i * 288 + l] = attnS[l];
}

// ---------------- V accumulation: one token per 256-thread block ----------------
__global__ __launch_bounds__(256) void vaccum_kernel(
    const float* __restrict__ v0, const float* __restrict__ v1,
    const float* __restrict__ nv0, const float* __restrict__ nv1)
{
    const int i = blockIdx.x;
    const int t = threadIdx.x;

    __shared__ float aS[NH * NJ];
    __shared__ const float* vp0S[NJ];
    __shared__ const float* vp1S[NJ];
    __shared__ __align__(16) float red[512];

    // FIX: strided load of all 272 weights
    for (int l = t; l < NH * NJ; l += 256)
        aS[l] = g_attn[(size_t)i * 288 + l];
    if (t >= 16 && t < 16 + NJ) {
        int j = t - 16;
        if (j == 0) {
            vp0S[0] = nv0; vp1S[0] = nv1;
        } else if (j == 1) {
            vp0S[1] = g_skv0 + (size_t)i * 256 + 128;
            vp1S[1] = g_skv1 + (size_t)i * 768 + 384;
        } else {
            size_t r = (size_t)i * NN + (j - 2);
            vp0S[j] = v0 + r * 128;
            vp1S[j] = v1 + r * 384;
        }
    }
    __syncthreads();

    const int g  = t >> 7;        // 0/1: j parity
    const int tl = t & 127;
    const bool isV1 = (tl < 96);
    const int off = isV1 ? 4 * tl : 4 * (tl - 96);
    const int hv  = isV1 ? (tl / 12) : ((tl - 96) / 4);
    const float* const* vtab = isV1 ? vp1S : vp0S;

    float4 acc = make_float4(0.f, 0.f, 0.f, 0.f);
    float4 cur = *(const float4*)(vtab[g] + off);
    float4 nx1 = make_float4(0.f, 0.f, 0.f, 0.f);
    if (g + 2 < NJ) nx1 = *(const float4*)(vtab[g + 2] + off);
    #pragma unroll 1
    for (int j = g; j < NJ; j += 2) {
        float4 nx2 = make_float4(0.f, 0.f, 0.f, 0.f);
        int jn = j + 4;
        if (jn < NJ) nx2 = *(const float4*)(vtab[jn] + off);
        float wgt = aS[hv * NJ + j];
        acc.x = fmaf(wgt, cur.x, acc.x);
        acc.y = fmaf(wgt, cur.y, acc.y);
        acc.z = fmaf(wgt, cur.z, acc.z);
        acc.w = fmaf(wgt, cur.w, acc.w);
        cur = nx1; nx1 = nx2;
    }
    if (g == 1) ((float4*)red)[tl] = acc;
    __syncthreads();
    if (g == 0) {
        float4 o = ((const float4*)red)[tl];
        acc.x += o.x; acc.y += o.y; acc.z += o.z; acc.w += o.w;
        if (isV1) *(float4*)(g_out1 + (size_t)i * 384 + off) = acc;
        else      *(float4*)(g_out0 + (size_t)i * 128 + off) = acc;
    }
}

// ---------------- launch ----------------
extern "C" void kernel_launch(void* const* d_in, const int* in_sizes, int n_in,
                              void* d_out, int out_size)
{
    const float* q0     = (const float*)d_in[0];
    const float* k0     = (const float*)d_in[1];
    const float* v0     = (const float*)d_in[2];
    const float* q1     = (const float*)d_in[3];
    const float* k1     = (const float*)d_in[4];
    const float* v1     = (const float*)d_in[5];
    const float* feats0 = (const float*)d_in[6];
    const float* feats1 = (const float*)d_in[7];
    const float* edges  = (const float*)d_in[8];
    const float* Wskv0  = (const float*)d_in[9];
    const float* Wskv1  = (const float*)d_in[10];
    const float* Wbias  = (const float*)d_in[11];
    const float* sbias  = (const float*)d_in[12];
    const float* nbias  = (const float*)d_in[13];
    const float* nk0    = (const float*)d_in[14];
    const float* nv0    = (const float*)d_in[15];
    const float* nk1    = (const float*)d_in[16];
    const float* nv1    = (const float*)d_in[17];
    const float* hw1    = (const float*)d_in[18];
    const float* Wout0  = (const float*)d_in[19];
    const float* Wout1  = (const float*)d_in[20];
    const void*  nbm    = d_in[21];
    float* out = (float*)d_out;

    skv_fused_kernel<<<dim3(256 / BN, NTOK / BM, 4), 128>>>(
        feats0, Wskv0, feats1, Wskv1, (const unsigned int*)nbm);

    logits_kernel<<<NTOK, 256>>>(q0, q1, k0, k1, edges, Wbias,
                                 sbias, nbias, nk0, nk1, hw1, nbm);

    vaccum_kernel<<<NTOK, 256>>>(v0, v1, nv0, nv1);

    out_fused_kernel<<<dim3(128 / BN, NTOK / BM, 4), 128>>>(Wout0, Wout1, out);
}